// round 16
// baseline (speedup 1.0000x reference)
#include <cuda_runtime.h>
#include <cstdint>

// HiearchSoft: out[b] = sum_l [ c_l*log_sigmoid(z_bl) + (1-c_l)*log_sigmoid(-z_bl) ]
// where z_bl = dot(xw[b,:], W[h_path[l],:]),  D=128, L=20.
//
// Strategy: block-level gather of the 20 W rows into SMEM (10KB), 2 threads per
// xw row (64 dims each), packed f32x2 FMA accumulation (20 packed accs),
// shfl_xor(16) pair reduction, stable fused log-sigmoid epilogue.

#define FMA_F32X2(acc, a, b) \
    asm("fma.rn.f32x2 %0, %1, %2, %0;" : "+l"(acc) : "l"(a), "l"(b))

#define UNPACK_F32X2(lo, hi, in) \
    asm("mov.b64 {%0, %1}, %2;" : "=f"(lo), "=f"(hi) : "l"(in))

static constexpr int D      = 128;   // embedding dim
static constexpr int LPATH  = 20;    // path length
static constexpr int ROWS_PER_BLOCK = 128;   // 256 threads, 2 per row
static constexpr int THREADS = 256;

__global__ void __launch_bounds__(THREADS, 1)
hiearchsoft_kernel(const float* __restrict__ xw,
                   const float* __restrict__ W,
                   const float* __restrict__ h_code,
                   const int*   __restrict__ h_path,
                   float* __restrict__ out,
                   int B)
{
    // ---- shared: gathered path weights (row-major, 20 x 128) + codes ----
    __shared__ __align__(16) float ws[LPATH * D];   // 10240 B
    __shared__ float sc[LPATH];

    const int tid = threadIdx.x;

    if (tid < LPATH) sc[tid] = h_code[tid];

    // gather 20 rows of W as float4 (640 float4 total, 256 threads)
    #pragma unroll
    for (int idx = tid; idx < LPATH * (D / 4); idx += THREADS) {
        const int l = idx >> 5;          // idx / 32
        const int j = idx & 31;          // float4 within row
        const float4* src = reinterpret_cast<const float4*>(
            W + (size_t)h_path[l] * D);
        reinterpret_cast<float4*>(ws)[idx] = src[j];
    }
    __syncthreads();

    // ---- thread mapping: 2 threads per row; q = lane>>4 so every 8-lane
    //      LDS phase reads one uniform address (broadcast, conflict-free) ----
    const int lane = tid & 31;
    const int warp = tid >> 5;
    const int q    = lane >> 4;          // which half of D
    const int r15  = lane & 15;          // row within warp's 16-row group
    int row = blockIdx.x * ROWS_PER_BLOCK + warp * 16 + r15;
    const bool valid = (row < B);
    if (!valid) row = B - 1;             // clamp: all lanes must reach shuffles

    // x pointer: this thread's 64-float half-row, read as 16B packed-pair units
    const ulonglong2* __restrict__ xr = reinterpret_cast<const ulonglong2*>(
        xw + (size_t)row * D + q * (D / 2));
    const ulonglong2* __restrict__ wsp =
        reinterpret_cast<const ulonglong2*>(ws);

    unsigned long long acc[LPATH];
    #pragma unroll
    for (int l = 0; l < LPATH; l++) acc[l] = 0ULL;   // packed (0.f, 0.f)

    const int wbase = q * 16;            // 16B-unit offset of this half in a row

    #pragma unroll 4
    for (int i = 0; i < 16; i++) {       // 16 x 16B = 64 floats
        const ulonglong2 xv = xr[i];
        #pragma unroll
        for (int l = 0; l < LPATH; l++) {
            const ulonglong2 wv = wsp[l * (D / 4) + wbase + i];
            FMA_F32X2(acc[l], xv.x, wv.x);
            FMA_F32X2(acc[l], xv.y, wv.y);
        }
    }

    // ---- collapse packed lanes + pair reduction across the two half-rows ----
    float z[LPATH];
    #pragma unroll
    for (int l = 0; l < LPATH; l++) {
        float lo, hi;
        UNPACK_F32X2(lo, hi, acc[l]);
        float zz = lo + hi;
        zz += __shfl_xor_sync(0xffffffffu, zz, 16);
        z[l] = zz;
    }

    // ---- epilogue on the q==0 lane of each pair ----
    if (q == 0 && valid) {
        float sum = 0.f;
        #pragma unroll
        for (int l = 0; l < LPATH; l++) {
            const float c  = sc[l];
            const float zz = z[l];
            // c*log_sigmoid(z) + (1-c)*log_sigmoid(-z)
            //   = c*min(z,0) + (1-c)*min(-z,0) - log1p(exp(-|z|))
            const float az = fabsf(zz);
            const float lp = -log1pf(__expf(-az));
            sum += c * fminf(zz, 0.f) + (1.f - c) * fminf(-zz, 0.f) + lp;
        }
        out[row] = sum;
    }
}

extern "C" void kernel_launch(void* const* d_in, const int* in_sizes, int n_in,
                              void* d_out, int out_size)
{
    const float* xw     = (const float*)d_in[0];   // (B, 128) f32
    const float* W      = (const float*)d_in[1];   // (N, 128) f32
    const float* h_code = (const float*)d_in[2];   // (20,)    f32
    const int*   h_path = (const int*)  d_in[3];   // (20,)    i32
    float*       out    = (float*)d_out;           // (B, 1)   f32

    const int B = in_sizes[0] / D;
    const int blocks = (B + ROWS_PER_BLOCK - 1) / ROWS_PER_BLOCK;

    hiearchsoft_kernel<<<blocks, THREADS>>>(xw, W, h_code, h_path, out, B);
}